// round 2
// baseline (speedup 1.0000x reference)
#include <cuda_runtime.h>
#include <math.h>

#define NITERS 5
#define CC 128
#define HH 512
#define WW 512

// ---------------- persistent device state ----------------
__device__ double d_accA[29];   // [0..20] hess upper-tri, [21..26] grad, [27] cost, [28] mask count
__device__ double d_accC[2];    // [0] cost, [1] mask count (proposed pose)
__device__ float  d_R[9], d_t[3], d_Rn[9], d_tn[3];
__device__ double d_lam, d_lr, d_prev;

// transposed (H,W,C) scratch maps (static device allocation — legal)
__device__ float d_tf [CC * HH * WW];
__device__ float d_tgx[CC * HH * WW];
__device__ float d_tgy[CC * HH * WW];

__constant__ int c_HI[21] = {0,0,0,0,0,0, 1,1,1,1,1, 2,2,2,2, 3,3,3, 4,4, 5};
__constant__ int c_HJ[21] = {0,1,2,3,4,5, 1,2,3,4,5, 2,3,4,5, 3,4,5, 4,5, 5};

// ---------------- init ----------------
__global__ void k_init() {
    int t = threadIdx.x;
    if (t < 29) d_accA[t] = 0.0;
    if (t < 2)  d_accC[t] = 0.0;
    if (t == 0) {
        d_R[0]=1.f; d_R[1]=0.f; d_R[2]=0.f;
        d_R[3]=0.f; d_R[4]=1.f; d_R[5]=0.f;
        d_R[6]=0.f; d_R[7]=0.f; d_R[8]=1.f;
        d_t[0]=1.f; d_t[1]=1.f; d_t[2]=0.f;
        d_lam = 0.01; d_lr = 0.1; d_prev = 0.0;
    }
}

// ---------------- transpose (C,HW) -> (HW,C) for all three maps ----------------
#define TDIM 32
#define TROWS 8
__global__ void __launch_bounds__(TDIM*TROWS) k_transpose(
    const float* __restrict__ s0, const float* __restrict__ s1,
    const float* __restrict__ s2, int C, int HW)
{
    __shared__ float tile[TDIM][TDIM + 1];
    const float* src = (blockIdx.z == 0) ? s0 : ((blockIdx.z == 1) ? s1 : s2);
    float* dst = (blockIdx.z == 0) ? d_tf : ((blockIdx.z == 1) ? d_tgx : d_tgy);

    int hw0 = blockIdx.x * TDIM;
    int c0  = blockIdx.y * TDIM;

    #pragma unroll
    for (int r = threadIdx.y; r < TDIM; r += TROWS) {
        int c  = c0 + r;
        int hw = hw0 + threadIdx.x;
        if (c < C && hw < HW)
            tile[r][threadIdx.x] = src[(size_t)c * HW + hw];
    }
    __syncthreads();
    #pragma unroll
    for (int r = threadIdx.y; r < TDIM; r += TROWS) {
        int hw = hw0 + r;
        int c  = c0 + threadIdx.x;
        if (c < C && hw < HW)
            dst[(size_t)hw * C + c] = tile[threadIdx.x][r];
    }
}

// ---------------- accumulate: Hess/Grad/cost at current (R,t) ----------------
__global__ void __launch_bounds__(256) k_accum(
    const float* __restrict__ pts, const float* __restrict__ fref,
    const float* __restrict__ Km, int N, int C, int H, int W)
{
    __shared__ double sAcc[29];
    __shared__ float sR[9], sT[3];
    int tid = threadIdx.x;
    if (tid < 29) sAcc[tid] = 0.0;
    if (tid < 9)  sR[tid] = d_R[tid];
    if (tid < 3)  sT[tid] = d_t[tid];
    __syncthreads();

    int lane = tid & 31;
    int n = blockIdx.x * 8 + (tid >> 5);
    if (n < N) {
        float px = pts[3*n+0], py = pts[3*n+1], pz = pts[3*n+2];
        float X = sR[0]*px + sR[1]*py + sR[2]*pz + sT[0];
        float Y = sR[3]*px + sR[4]*py + sR[5]*pz + sT[1];
        float Z = sR[6]*px + sR[7]*py + sR[8]*pz + sT[2];
        float fx = Km[0], cx = Km[2], fy = Km[4], cy = Km[5];
        float u = fx*X + cx*Z;
        float v = fy*Y + cy*Z;
        int xi = (int)rintf(__fdiv_rn(u, Z)) - 1;
        int yi = (int)rintf(__fdiv_rn(v, Z)) - 1;
        if (xi >= 0 && yi >= 0 && xi < H && yi < W) {
            int xc = xi < (W-1) ? xi : (W-1);
            int yc = yi < (H-1) ? yi : (H-1);
            size_t base = ((size_t)yc * W + xc) * (size_t)C;
            float4 f4 = ((const float4*)(d_tf  + base))[lane];
            float4 a4 = ((const float4*)(d_tgx + base))[lane];
            float4 b4 = ((const float4*)(d_tgy + base))[lane];
            float4 r4 = ((const float4*)(fref + (size_t)n * C))[lane];

            float saa=0.f, sab=0.f, sbb=0.f, sae=0.f, sbe=0.f, see=0.f;
            {
                float e;
                e = f4.x - r4.x;
                saa = fmaf(a4.x,a4.x,saa); sab = fmaf(a4.x,b4.x,sab); sbb = fmaf(b4.x,b4.x,sbb);
                sae = fmaf(a4.x,e,sae);    sbe = fmaf(b4.x,e,sbe);    see = fmaf(e,e,see);
                e = f4.y - r4.y;
                saa = fmaf(a4.y,a4.y,saa); sab = fmaf(a4.y,b4.y,sab); sbb = fmaf(b4.y,b4.y,sbb);
                sae = fmaf(a4.y,e,sae);    sbe = fmaf(b4.y,e,sbe);    see = fmaf(e,e,see);
                e = f4.z - r4.z;
                saa = fmaf(a4.z,a4.z,saa); sab = fmaf(a4.z,b4.z,sab); sbb = fmaf(b4.z,b4.z,sbb);
                sae = fmaf(a4.z,e,sae);    sbe = fmaf(b4.z,e,sbe);    see = fmaf(e,e,see);
                e = f4.w - r4.w;
                saa = fmaf(a4.w,a4.w,saa); sab = fmaf(a4.w,b4.w,sab); sbb = fmaf(b4.w,b4.w,sbb);
                sae = fmaf(a4.w,e,sae);    sbe = fmaf(b4.w,e,sbe);    see = fmaf(e,e,see);
            }
            #pragma unroll
            for (int s = 16; s; s >>= 1) {
                saa += __shfl_xor_sync(0xffffffffu, saa, s);
                sab += __shfl_xor_sync(0xffffffffu, sab, s);
                sbb += __shfl_xor_sync(0xffffffffu, sbb, s);
                sae += __shfl_xor_sync(0xffffffffu, sae, s);
                sbe += __shfl_xor_sync(0xffffffffu, sbe, s);
                see += __shfl_xor_sync(0xffffffffu, see, s);
            }
            float rz = 1.0f / Z;
            float a2 = -fx * X * rz * rz;
            float b2 = -fy * Y * rz * rz;
            float r0[6], r1[6];
            r0[0] = fx*rz;  r0[1] = 0.f;    r0[2] = a2;
            r0[3] = a2*Y;   r0[4] = fx - a2*X;  r0[5] = -fx*Y*rz;
            r1[0] = 0.f;    r1[1] = fy*rz;  r1[2] = b2;
            r1[3] = -(fy - b2*Y); r1[4] = -b2*X; r1[5] = fy*X*rz;

            if (lane < 29) {
                double val;
                if (lane < 21) {
                    int i = c_HI[lane], j = c_HJ[lane];
                    val = (double)saa * r0[i] * r0[j]
                        + (double)sab * ((double)r0[i]*r1[j] + (double)r1[i]*r0[j])
                        + (double)sbb * r1[i] * r1[j];
                } else if (lane < 27) {
                    int i = lane - 21;
                    val = (double)sae * r0[i] + (double)sbe * r1[i];
                } else if (lane == 27) {
                    val = 0.5 * (double)see;
                } else {
                    val = 1.0;
                }
                atomicAdd(&sAcc[lane], val);
            }
        }
    }
    __syncthreads();
    if (tid < 29) {
        double v = sAcc[tid];
        if (v != 0.0) atomicAdd(&d_accA[tid], v);
    }
}

// ---------------- cost at proposed (Rn,tn) ----------------
__global__ void __launch_bounds__(256) k_cost(
    const float* __restrict__ pts, const float* __restrict__ fref,
    const float* __restrict__ Km, int N, int C, int H, int W)
{
    __shared__ double sAcc[2];
    __shared__ float sR[9], sT[3];
    int tid = threadIdx.x;
    if (tid < 2) sAcc[tid] = 0.0;
    if (tid < 9) sR[tid] = d_Rn[tid];
    if (tid < 3) sT[tid] = d_tn[tid];
    __syncthreads();

    int lane = tid & 31;
    int n = blockIdx.x * 8 + (tid >> 5);
    if (n < N) {
        float px = pts[3*n+0], py = pts[3*n+1], pz = pts[3*n+2];
        float X = sR[0]*px + sR[1]*py + sR[2]*pz + sT[0];
        float Y = sR[3]*px + sR[4]*py + sR[5]*pz + sT[1];
        float Z = sR[6]*px + sR[7]*py + sR[8]*pz + sT[2];
        float fx = Km[0], cx = Km[2], fy = Km[4], cy = Km[5];
        float u = fx*X + cx*Z;
        float v = fy*Y + cy*Z;
        int xi = (int)rintf(__fdiv_rn(u, Z)) - 1;
        int yi = (int)rintf(__fdiv_rn(v, Z)) - 1;
        if (xi >= 0 && yi >= 0 && xi < H && yi < W) {
            int xc = xi < (W-1) ? xi : (W-1);
            int yc = yi < (H-1) ? yi : (H-1);
            size_t base = ((size_t)yc * W + xc) * (size_t)C;
            float4 f4 = ((const float4*)(d_tf + base))[lane];
            float4 r4 = ((const float4*)(fref + (size_t)n * C))[lane];
            float see = 0.f, e;
            e = f4.x - r4.x; see = fmaf(e,e,see);
            e = f4.y - r4.y; see = fmaf(e,e,see);
            e = f4.z - r4.z; see = fmaf(e,e,see);
            e = f4.w - r4.w; see = fmaf(e,e,see);
            #pragma unroll
            for (int s = 16; s; s >>= 1)
                see += __shfl_xor_sync(0xffffffffu, see, s);
            if (lane == 0) atomicAdd(&sAcc[0], 0.5 * (double)see);
            if (lane == 1) atomicAdd(&sAcc[1], 1.0);
        }
    }
    __syncthreads();
    if (tid < 2) {
        double v = sAcc[tid];
        if (v != 0.0) atomicAdd(&d_accC[tid], v);
    }
}

// ---------------- LM solve (6x6), so3exp, propose pose ----------------
__global__ void k_solve(int setPrev)
{
    if (setPrev) {
        d_prev = d_accA[27] / fmax(d_accA[28], 1.0);
    }
    double Hm[6][6];
    int k = 0;
    for (int i = 0; i < 6; i++)
        for (int j = i; j < 6; j++) { Hm[i][j] = Hm[j][i] = d_accA[k++]; }
    double G[6];
    for (int i = 0; i < 6; i++) G[i] = d_accA[21 + i];
    double lam = d_lam;
    for (int i = 0; i < 6; i++) Hm[i][i] = Hm[i][i] + (Hm[i][i] + 1e-9) * lam;

    double M[6][12];
    for (int i = 0; i < 6; i++) {
        for (int j = 0; j < 6; j++) { M[i][j] = Hm[i][j]; M[i][6+j] = (i==j) ? 1.0 : 0.0; }
    }
    for (int p = 0; p < 6; p++) {
        int piv = p;
        double mx = fabs(M[p][p]);
        for (int r = p+1; r < 6; r++) { double a = fabs(M[r][p]); if (a > mx) { mx = a; piv = r; } }
        if (piv != p) for (int j = 0; j < 12; j++) { double tmp = M[p][j]; M[p][j] = M[piv][j]; M[piv][j] = tmp; }
        double inv = 1.0 / M[p][p];
        for (int j = 0; j < 12; j++) M[p][j] *= inv;
        for (int r = 0; r < 6; r++) {
            if (r == p) continue;
            double f = M[r][p];
            if (f != 0.0) for (int j = 0; j < 12; j++) M[r][j] -= f * M[p][j];
        }
    }
    double dlt[6];
    double lr = d_lr;
    for (int i = 0; i < 6; i++) {
        double s = 0.0;
        for (int j = 0; j < 6; j++) s += M[i][6+j] * G[j];
        dlt[i] = -lr * s;
    }
    double w0 = dlt[3], w1 = dlt[4], w2 = dlt[5];
    double th2 = w0*w0 + w1*w1 + w2*w2;
    double th  = sqrt(th2 + 1e-24);
    double A = sin(th) / th;
    double B = (1.0 - cos(th)) / (th2 + 1e-24);
    double Wm[3][3] = {{0.0,-w2,w1},{w2,0.0,-w0},{-w1,w0,0.0}};
    double W2[3][3];
    for (int i = 0; i < 3; i++)
        for (int j = 0; j < 3; j++) {
            double s = 0.0;
            for (int q = 0; q < 3; q++) s += Wm[i][q]*Wm[q][j];
            W2[i][j] = s;
        }
    double dr[3][3];
    for (int i = 0; i < 3; i++)
        for (int j = 0; j < 3; j++)
            dr[i][j] = (i==j ? 1.0 : 0.0) + A*Wm[i][j] + B*W2[i][j];
    double Ro[9], to[3];
    for (int i = 0; i < 9; i++) Ro[i] = (double)d_R[i];
    for (int i = 0; i < 3; i++) to[i] = (double)d_t[i];
    for (int i = 0; i < 3; i++) {
        for (int j = 0; j < 3; j++) {
            double s = 0.0;
            for (int q = 0; q < 3; q++) s += dr[i][q] * Ro[3*q + j];
            d_Rn[3*i + j] = (float)s;
        }
        double s = 0.0;
        for (int q = 0; q < 3; q++) s += dr[i][q] * to[q];
        d_tn[i] = (float)(s + dlt[i]);
    }
    for (int i = 0; i < 29; i++) d_accA[i] = 0.0;
}

// ---------------- accept/reject + schedules ----------------
__global__ void k_update(int writeOut, float* __restrict__ out)
{
    double nc = d_accC[0] / fmax(d_accC[1], 1.0);
    int worse = (nc > d_prev) ? 1 : 0;
    double lam = d_lam * (worse ? 10.0 : 0.1);
    lam = fmin(fmax(lam, 1e-6), 1e4);
    d_lam = lam;
    if (worse) {
        double lr = 0.1 * d_lr;
        d_lr = fmin(fmax(lr, 1e-3), 1.0);
    } else {
        d_lr = 0.1;
        for (int i = 0; i < 9; i++) d_R[i] = d_Rn[i];
        for (int i = 0; i < 3; i++) d_t[i] = d_tn[i];
        d_prev = nc;
    }
    d_accC[0] = 0.0; d_accC[1] = 0.0;
    if (writeOut) {
        for (int i = 0; i < 9; i++)  out[i]     = d_R[i];
        for (int i = 0; i < 3; i++)  out[9 + i] = d_t[i];
    }
}

// ---------------- launch ----------------
extern "C" void kernel_launch(void* const* d_in, const int* in_sizes, int n_in,
                              void* d_out, int out_size)
{
    const float* pts  = (const float*)d_in[0];
    const float* fref = (const float*)d_in[1];
    const float* fmap = (const float*)d_in[2];
    const float* gx   = (const float*)d_in[3];
    const float* gy   = (const float*)d_in[4];
    const float* Km   = (const float*)d_in[5];

    int N  = in_sizes[0] / 3;
    int C  = in_sizes[1] / N;
    int HW = in_sizes[2] / C;
    int H  = (int)(sqrt((double)HW) + 0.5);
    int W  = HW / H;

    int blocks = (N + 7) / 8;

    k_init<<<1, 32>>>();

    dim3 tgrid((HW + TDIM - 1) / TDIM, (C + TDIM - 1) / TDIM, 3);
    dim3 tblk(TDIM, TROWS);
    k_transpose<<<tgrid, tblk>>>(fmap, gx, gy, C, HW);

    for (int it = 0; it < NITERS; it++) {
        k_accum<<<blocks, 256>>>(pts, fref, Km, N, C, H, W);
        k_solve<<<1, 1>>>(it == 0 ? 1 : 0);
        k_cost<<<blocks, 256>>>(pts, fref, Km, N, C, H, W);
        k_update<<<1, 1>>>(it == NITERS - 1 ? 1 : 0, (float*)d_out);
    }
}

// round 3
// speedup vs baseline: 1.6227x; 1.6227x over previous
#include <cuda_runtime.h>
#include <math.h>

#define NITERS 5

// ---------------- persistent device state ----------------
__device__ double d_accCur[29];  // [0..20] hess upper-tri, [21..26] grad, [27] cost*2 sum, [28] mask count
__device__ double d_accProp[29];
__device__ float  d_R[9], d_t[3], d_Rn[9], d_tn[3];
__device__ double d_lam, d_lr, d_prev;

__constant__ int c_HI[21] = {0,0,0,0,0,0, 1,1,1,1,1, 2,2,2,2, 3,3,3, 4,4, 5};
__constant__ int c_HJ[21] = {0,1,2,3,4,5, 1,2,3,4,5, 2,3,4,5, 3,4,5, 4,5, 5};

__device__ __forceinline__ int triidx(int i, int j) {   // i<=j
    return i * (13 - i) / 2 + (j - i);
}

// ---------------- init ----------------
__global__ void k_init() {
    int t = threadIdx.x;
    if (t < 29) { d_accCur[t] = 0.0; d_accProp[t] = 0.0; }
    if (t == 0) {
        d_R[0]=1.f; d_R[1]=0.f; d_R[2]=0.f;
        d_R[3]=0.f; d_R[4]=1.f; d_R[5]=0.f;
        d_R[6]=0.f; d_R[7]=0.f; d_R[8]=1.f;
        d_t[0]=1.f; d_t[1]=1.f; d_t[2]=0.f;
        d_lam = 0.01; d_lr = 0.1; d_prev = 0.0;
    }
}

// ---------------- gather + accumulate Hess/Grad/cost at a pose ----------------
__global__ void __launch_bounds__(256) k_gather(
    const float* __restrict__ pts, const float* __restrict__ fref,
    const float* __restrict__ fmap, const float* __restrict__ gx,
    const float* __restrict__ gy, const float* __restrict__ Km,
    int N, int C, int H, int W, int proposed)
{
    __shared__ double sAcc[29];
    __shared__ float sR[9], sT[3];
    int tid = threadIdx.x;
    if (tid < 29) sAcc[tid] = 0.0;
    if (tid < 9)  sR[tid] = proposed ? d_Rn[tid] : d_R[tid];
    if (tid < 3)  sT[tid] = proposed ? d_tn[tid] : d_t[tid];
    __syncthreads();

    int lane = tid & 31;
    int n = blockIdx.x * 8 + (tid >> 5);
    if (n < N) {
        float px = pts[3*n+0], py = pts[3*n+1], pz = pts[3*n+2];
        float X = sR[0]*px + sR[1]*py + sR[2]*pz + sT[0];
        float Y = sR[3]*px + sR[4]*py + sR[5]*pz + sT[1];
        float Z = sR[6]*px + sR[7]*py + sR[8]*pz + sT[2];
        float fx = Km[0], cx = Km[2], fy = Km[4], cy = Km[5];
        float u = fx*X + cx*Z;
        float v = fy*Y + cy*Z;
        int xi = (int)rintf(__fdiv_rn(u, Z)) - 1;
        int yi = (int)rintf(__fdiv_rn(v, Z)) - 1;
        // mask per reference: (x>=0)&(y>=0)&(x<H)&(y<W)
        if (xi >= 0 && yi >= 0 && xi < H && yi < W) {
            int xc = xi < (W-1) ? xi : (W-1);
            int yc = yi < (H-1) ? yi : (H-1);
            size_t off = (size_t)yc * W + xc;
            size_t HW = (size_t)H * W;
            float saa=0.f, sab=0.f, sbb=0.f, sae=0.f, sbe=0.f, see=0.f;
            #pragma unroll 4
            for (int c = lane; c < C; c += 32) {
                float f = __ldg(&fmap[(size_t)c*HW + off]);
                float a = __ldg(&gx  [(size_t)c*HW + off]);
                float b = __ldg(&gy  [(size_t)c*HW + off]);
                float e = f - fref[(size_t)n*C + c];
                saa = fmaf(a,a,saa); sab = fmaf(a,b,sab); sbb = fmaf(b,b,sbb);
                sae = fmaf(a,e,sae); sbe = fmaf(b,e,sbe); see = fmaf(e,e,see);
            }
            #pragma unroll
            for (int s = 16; s; s >>= 1) {
                saa += __shfl_xor_sync(0xffffffffu, saa, s);
                sab += __shfl_xor_sync(0xffffffffu, sab, s);
                sbb += __shfl_xor_sync(0xffffffffu, sbb, s);
                sae += __shfl_xor_sync(0xffffffffu, sae, s);
                sbe += __shfl_xor_sync(0xffffffffu, sbe, s);
                see += __shfl_xor_sync(0xffffffffu, see, s);
            }
            float rz = 1.0f / Z;
            float a2 = -fx * X * rz * rz;
            float b2 = -fy * Y * rz * rz;
            float r0[6], r1[6];
            r0[0] = fx*rz;  r0[1] = 0.f;        r0[2] = a2;
            r0[3] = a2*Y;   r0[4] = fx - a2*X;  r0[5] = -fx*Y*rz;
            r1[0] = 0.f;    r1[1] = fy*rz;      r1[2] = b2;
            r1[3] = -(fy - b2*Y); r1[4] = -b2*X; r1[5] = fy*X*rz;

            if (lane < 29) {
                double val;
                if (lane < 21) {
                    int i = c_HI[lane], j = c_HJ[lane];
                    val = (double)saa * r0[i] * r0[j]
                        + (double)sab * ((double)r0[i]*r1[j] + (double)r1[i]*r0[j])
                        + (double)sbb * r1[i] * r1[j];
                } else if (lane < 27) {
                    int i = lane - 21;
                    val = (double)sae * r0[i] + (double)sbe * r1[i];
                } else if (lane == 27) {
                    val = 0.5 * (double)see;
                } else {
                    val = 1.0;
                }
                atomicAdd(&sAcc[lane], val);
            }
        }
    }
    __syncthreads();
    if (tid < 29) {
        double v = sAcc[tid];
        double* acc = proposed ? d_accProp : d_accCur;
        if (v != 0.0) atomicAdd(&acc[tid], v);
    }
}

// ---------------- update (accept/reject) + warp-parallel LM solve ----------------
__global__ void k_step(int first, int last, float* __restrict__ out)
{
    const unsigned fullm = 0xffffffffu;
    int lane = threadIdx.x;

    double lam = d_lam, lr = d_lr, prev = d_prev;
    int accept = 0;
    if (first) {
        prev = d_accCur[27] / fmax(d_accCur[28], 1.0);
    } else {
        double nc = d_accProp[27] / fmax(d_accProp[28], 1.0);
        int worse = (nc > prev) ? 1 : 0;
        lam = fmin(fmax(lam * (worse ? 10.0 : 0.1), 1e-6), 1e4);
        lr = worse ? fmin(fmax(0.1 * lr, 1e-3), 1.0) : 0.1;
        if (!worse) { accept = 1; prev = nc; }
    }
    if (lane == 0) { d_lam = lam; d_lr = lr; d_prev = prev; }
    if (accept) {
        if (lane < 29) d_accCur[lane] = d_accProp[lane];
        if (lane < 9)  d_R[lane] = d_Rn[lane];
        if (lane < 3)  d_t[lane] = d_tn[lane];
    }

    if (last) {
        if (lane < 9) out[lane]     = accept ? d_Rn[lane] : d_R[lane];
        if (lane < 3) out[9 + lane] = accept ? d_tn[lane] : d_t[lane];
        return;
    }

    const double* srcA = accept ? d_accProp : d_accCur;

    // ---- warp-parallel Gauss-Jordan on [Hd | G], lanes 0..6 own columns ----
    double col[6];
    #pragma unroll
    for (int r = 0; r < 6; r++) col[r] = 0.0;
    if (lane < 6) {
        #pragma unroll
        for (int r = 0; r < 6; r++) {
            int i = r < lane ? r : lane, j = r < lane ? lane : r;
            double a = srcA[triidx(i, j)];
            col[r] = (r == lane) ? (a + (a + 1e-9) * lam) : a;
        }
    } else if (lane == 6) {
        #pragma unroll
        for (int r = 0; r < 6; r++) col[r] = srcA[21 + r];
    }
    #pragma unroll
    for (int p = 0; p < 6; p++) {
        double pv = __shfl_sync(fullm, col[p], p);
        double inv = 1.0 / pv;
        double f[6];
        #pragma unroll
        for (int r = 0; r < 6; r++) f[r] = __shfl_sync(fullm, col[r], p);
        col[p] *= inv;
        #pragma unroll
        for (int r = 0; r < 6; r++)
            if (r != p) col[r] -= f[r] * col[p];
    }
    double dlt[6];
    #pragma unroll
    for (int r = 0; r < 6; r++) dlt[r] = -lr * __shfl_sync(fullm, col[r], 6);

    __syncwarp();
    if (lane == 0) {
        // so3exp(dw)
        double w0 = dlt[3], w1 = dlt[4], w2 = dlt[5];
        double th2 = w0*w0 + w1*w1 + w2*w2;
        double th  = sqrt(th2 + 1e-24);
        double A = sin(th) / th;
        double B = (1.0 - cos(th)) / (th2 + 1e-24);
        double Wm[3][3] = {{0.0,-w2,w1},{w2,0.0,-w0},{-w1,w0,0.0}};
        double W2[3][3];
        #pragma unroll
        for (int i = 0; i < 3; i++)
            #pragma unroll
            for (int j = 0; j < 3; j++) {
                double s = 0.0;
                for (int q = 0; q < 3; q++) s += Wm[i][q]*Wm[q][j];
                W2[i][j] = s;
            }
        double dr[3][3];
        #pragma unroll
        for (int i = 0; i < 3; i++)
            #pragma unroll
            for (int j = 0; j < 3; j++)
                dr[i][j] = (i==j ? 1.0 : 0.0) + A*Wm[i][j] + B*W2[i][j];
        // current (possibly just-accepted) pose
        double Ro[9], to[3];
        #pragma unroll
        for (int i = 0; i < 9; i++) Ro[i] = (double)(accept ? d_Rn[i] : d_R[i]);
        #pragma unroll
        for (int i = 0; i < 3; i++) to[i] = (double)(accept ? d_tn[i] : d_t[i]);
        float Rn[9], tn[3];
        #pragma unroll
        for (int i = 0; i < 3; i++) {
            #pragma unroll
            for (int j = 0; j < 3; j++) {
                double s = 0.0;
                for (int q = 0; q < 3; q++) s += dr[i][q] * Ro[3*q + j];
                Rn[3*i + j] = (float)s;
            }
            double s = 0.0;
            for (int q = 0; q < 3; q++) s += dr[i][q] * to[q];
            tn[i] = (float)(s + dlt[i]);
        }
        #pragma unroll
        for (int i = 0; i < 9; i++) d_Rn[i] = Rn[i];
        #pragma unroll
        for (int i = 0; i < 3; i++) d_tn[i] = tn[i];
    }
    // reset proposal accumulators for the next gather
    if (lane < 29) d_accProp[lane] = 0.0;
}

// ---------------- launch ----------------
extern "C" void kernel_launch(void* const* d_in, const int* in_sizes, int n_in,
                              void* d_out, int out_size)
{
    const float* pts  = (const float*)d_in[0];
    const float* fref = (const float*)d_in[1];
    const float* fmap = (const float*)d_in[2];
    const float* gx   = (const float*)d_in[3];
    const float* gy   = (const float*)d_in[4];
    const float* Km   = (const float*)d_in[5];

    int N  = in_sizes[0] / 3;
    int C  = in_sizes[1] / N;
    int HW = in_sizes[2] / C;
    int H  = (int)(sqrt((double)HW) + 0.5);
    int W  = HW / H;

    int blocks = (N + 7) / 8;

    k_init<<<1, 32>>>();
    // Hess/Grad/cost at initial pose -> accCur
    k_gather<<<blocks, 256>>>(pts, fref, fmap, gx, gy, Km, N, C, H, W, 0);
    // first solve (sets prev_cost, proposes pose for iter 0)
    k_step<<<1, 32>>>(1, 0, (float*)d_out);
    for (int it = 0; it < NITERS; it++) {
        // evaluate proposed pose: cost AND Hess/Grad in one pass -> accProp
        k_gather<<<blocks, 256>>>(pts, fref, fmap, gx, gy, Km, N, C, H, W, 1);
        // accept/reject + (unless last) solve for next proposal
        k_step<<<1, 32>>>(0, it == NITERS - 1 ? 1 : 0, (float*)d_out);
    }
}